// round 14
// baseline (speedup 1.0000x reference)
#include <cuda_runtime.h>
#include <math.h>

#define CB 32
#define CS 128
#define CH 512
#define CG 2048
#define CV 32000
#define CT 48
#define CBK 128   // B*BEAM

// ----------------- device scratch (no runtime allocation) -------------------
__device__ float g_X[CB*CS*CH];
__device__ float g_ZX[CB*CS*CG];
__device__ float g_enc_out[CB*CS*CH];
__device__ float g_keys[CB*CS*CH];
__device__ float g_eh[CB*CH];
__device__ float g_eh2[CB*CH];
__device__ float g_ec[CB*CH];
__device__ float g_ec2[CB*CH];
__device__ float g_Wz[1536*CG];
__device__ float g_part[4*CBK*CG];
__device__ float g_XC[CBK*1536];
__device__ float g_CA[CBK*1024];
__device__ float g_h[CBK*CH];
__device__ float g_c[CBK*CH];
__device__ float g_cell[CBK*CH];
__device__ float g_cnew[CBK*CH];
__device__ float g_attn[CBK*CH];
__device__ float g_attn_new[CBK*CH];
__device__ float g_logits[CBK*CV];
__device__ float g_rmax[CBK];
__device__ float g_lse[CBK];
__device__ float g_cum[CBK];
__device__ int   g_fin[CBK];
__device__ int   g_tok[CBK];
__device__ int   g_parents[CT*CBK];
__device__ int   g_toksh[CT*CBK];
__device__ int   g_diag;

__device__ __forceinline__ float sigf(float x){ return 1.0f/(1.0f+expf(-x)); }

__device__ __forceinline__ const float* selA(int s){
    switch(s){ case 0: return g_X; case 1: return g_enc_out;
               case 2: return g_XC; case 3: return g_CA; default: return g_attn_new; }
}
__device__ __forceinline__ float* selC(int s){
    switch(s){ case 0: return g_ZX; case 1: return g_keys;
               case 2: return g_part; case 3: return g_part; default: return g_logits; }
}

// ----------------- setup / diagnostic kernels --------------------------------
__global__ void k_constf(float* o, int n, float val){
    int i = blockIdx.x*256 + threadIdx.x;
    if (i < n) o[i] = val;
}
__global__ void k_diag0(){ if (threadIdx.x == 0) g_diag = 0; }
__global__ void k_check_enc(){
    __shared__ float ss[256];
    __shared__ int bad;
    int tid = threadIdx.x;
    if (tid == 0) bad = 0;
    __syncthreads();
    float s = 0.f;
    for (int i = tid; i < 2048; i += 256){
        float v = g_enc_out[(size_t)i*1024 + 7];
        if (!isfinite(v)) bad = 1;
        s += fabsf(v);
    }
    ss[tid] = s;
    __syncthreads();
    for (int off = 128; off; off >>= 1){
        if (tid < off) ss[tid] += ss[tid+off];
        __syncthreads();
    }
    if (tid == 0 && (bad || ss[0] == 0.f)) atomicOr(&g_diag, 1);
}
__global__ void k_check_cum(){
    __shared__ int bad;
    int tid = threadIdx.x;
    if (tid == 0) bad = 0;
    __syncthreads();
    float v = g_cum[tid];
    if (!isfinite(v) || v < -1.0e7f) bad = 1;
    __syncthreads();
    if (tid == 0 && bad) atomicOr(&g_diag, 2);
}
__global__ void k_zero(){
    int i = blockIdx.x*512 + threadIdx.x;
    if (i < CB*CH){ g_eh[i]=0.f; g_ec[i]=0.f; }
}
__global__ void k_gatherX(const int* __restrict__ enc_in,
                          const float* __restrict__ emb){
    int r = blockIdx.x;
    int tok = enc_in[r];
    g_X[(size_t)r*CH + threadIdx.x]       = emb[(size_t)tok*CH + threadIdx.x];
    g_X[(size_t)r*CH + threadIdx.x + 256] = emb[(size_t)tok*CH + threadIdx.x + 256];
}
__global__ void k_catW(const float* __restrict__ Wd, const float* __restrict__ Ud){
    int i = blockIdx.x*1024 + threadIdx.x;
    if (i >= 1536*CG) return;
    int row = i / CG, col = i % CG;
    g_Wz[i] = (row < 1024) ? Wd[i] : Ud[(size_t)(row-1024)*CG + col];
}
__global__ void k_dec_init(){
    int bk = blockIdx.x, b = bk>>2, hid = threadIdx.x;
    g_h[bk*CH+hid]    = g_eh[b*CH+hid];
    g_c[bk*CH+hid]    = g_ec[b*CH+hid];
    g_attn[bk*CH+hid] = 0.f;
    if (hid == 0){
        g_cum[bk] = ((bk&3)==0) ? 0.f : -1e9f;
        g_fin[bk] = 0;
        g_tok[bk] = 1;
    }
}

// ---- GEMM: C = A·B, 64x64 tile, 4x4 micro, 256 threads ----------------------
__global__ void k_g64(int sel, const float* __restrict__ Bext,
                      int lda, int ldb, int ldc, int kspan, long long zstr){
    __shared__ float As[16][65];
    __shared__ float Bs[16][65];
    const float* A = selA(sel);
    const float* B = Bext ? Bext : (const float*)g_Wz;
    float* C = selC(sel) + (long long)blockIdx.z * zstr;
    const int bm = blockIdx.y * 64;
    const int bn = blockIdx.x * 64;
    const int k0 = blockIdx.z * kspan;
    const int tid = threadIdx.x;
    const int tx = tid & 15, ty = tid >> 4;
    float acc[4][4];
    #pragma unroll
    for (int i=0;i<4;i++)
        #pragma unroll
        for (int j=0;j<4;j++) acc[i][j]=0.f;
    for (int kc = 0; kc < kspan; kc += 16){
        #pragma unroll
        for (int r = 0; r < 4; r++){
            int i = tid + 256*r;
            int m  = i >> 4, kk = i & 15;
            As[kk][m] = A[(size_t)(bm+m)*lda + k0 + kc + kk];
        }
        #pragma unroll
        for (int r = 0; r < 4; r++){
            int i = tid + 256*r;
            int kk = i >> 6, n = i & 63;
            Bs[kk][n] = B[(size_t)(k0+kc+kk)*ldb + bn + n];
        }
        __syncthreads();
        #pragma unroll
        for (int kk = 0; kk < 16; kk++){
            float a0=As[kk][ty],    a1=As[kk][ty+16],
                  a2=As[kk][ty+32], a3=As[kk][ty+48];
            float b0=Bs[kk][tx],    b1=Bs[kk][tx+16],
                  b2=Bs[kk][tx+32], b3=Bs[kk][tx+48];
            acc[0][0]=fmaf(a0,b0,acc[0][0]); acc[0][1]=fmaf(a0,b1,acc[0][1]);
            acc[0][2]=fmaf(a0,b2,acc[0][2]); acc[0][3]=fmaf(a0,b3,acc[0][3]);
            acc[1][0]=fmaf(a1,b0,acc[1][0]); acc[1][1]=fmaf(a1,b1,acc[1][1]);
            acc[1][2]=fmaf(a1,b2,acc[1][2]); acc[1][3]=fmaf(a1,b3,acc[1][3]);
            acc[2][0]=fmaf(a2,b0,acc[2][0]); acc[2][1]=fmaf(a2,b1,acc[2][1]);
            acc[2][2]=fmaf(a2,b2,acc[2][2]); acc[2][3]=fmaf(a2,b3,acc[2][3]);
            acc[3][0]=fmaf(a3,b0,acc[3][0]); acc[3][1]=fmaf(a3,b1,acc[3][1]);
            acc[3][2]=fmaf(a3,b2,acc[3][2]); acc[3][3]=fmaf(a3,b3,acc[3][3]);
        }
        __syncthreads();
    }
    #pragma unroll
    for (int i=0;i<4;i++)
        #pragma unroll
        for (int j=0;j<4;j++)
            C[(size_t)(bm + ty + 16*i)*ldc + bn + tx + 16*j] = acc[i][j];
}

// ----------------- encoder LSTM step ----------------------------------------
__global__ void k_enc_step(const float* __restrict__ U, const float* __restrict__ bias,
                           int par, int t){
    __shared__ float hsT[256][33];
    const float* hin = par ? g_eh2 : g_eh;
    const float* cin = par ? g_ec2 : g_ec;
    float* hout = par ? g_eh : g_eh2;
    float* cout = par ? g_ec : g_ec2;
    int tid = threadIdx.x;
    int b = tid & 31, hl = tid >> 5;
    int hid = blockIdx.x*16 + hl;
    size_t zrow = (size_t)(b*CS + t)*CG;
    float zi = g_ZX[zrow + hid]        + bias[hid];
    float zf = g_ZX[zrow + 512 + hid]  + bias[512+hid];
    float zg = g_ZX[zrow + 1024 + hid] + bias[1024+hid];
    float zo = g_ZX[zrow + 1536 + hid] + bias[1536+hid];
    for (int kc = 0; kc < CH; kc += 256){
        for (int i = tid; i < 256*32; i += 512){
            int bb = i >> 8, kk = i & 255;
            hsT[kk][bb] = hin[bb*CH + kc + kk];
        }
        __syncthreads();
        #pragma unroll 4
        for (int k = 0; k < 256; k++){
            float hv = hsT[k][b];
            const float* Urow = U + (size_t)(kc+k)*CG + hid;
            zi = fmaf(hv, Urow[0],    zi);
            zf = fmaf(hv, Urow[512],  zf);
            zg = fmaf(hv, Urow[1024], zg);
            zo = fmaf(hv, Urow[1536], zo);
        }
        __syncthreads();
    }
    float ii = sigf(zi), ff = sigf(zf), gg = tanhf(zg), oo = sigf(zo);
    float cn = ff*cin[b*CH+hid] + ii*gg;
    cout[b*CH+hid] = cn;
    float hn = oo*tanhf(cn);
    hout[b*CH+hid] = hn;
    g_enc_out[(size_t)(b*CS+t)*CH + hid] = hn;
}

// ----------------- decoder helpers ------------------------------------------
__global__ void k_prep(const float* __restrict__ dec_emb){
    int bk = blockIdx.x;
    int tok = g_tok[bk];
    #pragma unroll
    for (int r = 0; r < 6; r++){
        int c = threadIdx.x + 256*r;
        float v;
        if (c < 512)       v = dec_emb[(size_t)tok*CH + c];
        else if (c < 1024) v = g_attn[bk*CH + c - 512];
        else               v = g_h[bk*CH + c - 1024];
        g_XC[(size_t)bk*1536 + c] = v;
    }
}
__global__ void k_dgate(const float* __restrict__ bias){
    int bk = blockIdx.x, hid = threadIdx.x;
    float zi = bias[hid], zf = bias[hid+512], zg = bias[hid+1024], zo = bias[hid+1536];
    #pragma unroll
    for (int z = 0; z < 4; z++){
        size_t base = (size_t)z*CBK*CG + (size_t)bk*CG;
        zi += g_part[base+hid];      zf += g_part[base+hid+512];
        zg += g_part[base+hid+1024]; zo += g_part[base+hid+1536];
    }
    float ii = sigf(zi), ff = sigf(zf), gg = tanhf(zg), oo = sigf(zo);
    float cn = ff*g_c[bk*CH+hid] + ii*gg;
    g_cnew[bk*CH+hid] = cn;
    g_cell[bk*CH+hid] = oo*tanhf(cn);
}
__global__ void k_attn(){
    __shared__ float cell[512];
    __shared__ float sc[128];
    __shared__ float red[128];
    __shared__ float al[128];
    int bk = blockIdx.x, b = bk >> 2;
    int tid = threadIdx.x;
    #pragma unroll
    for (int r = 0; r < 4; r++) cell[tid + 128*r] = g_cell[bk*CH + tid + 128*r];
    __syncthreads();
    {
        const float* kr = g_keys + (size_t)(b*CS + tid)*CH;
        float a = 0.f;
        #pragma unroll 4
        for (int h = 0; h < CH; h++) a = fmaf(cell[h], kr[h], a);
        sc[tid] = a; red[tid] = a;
    }
    __syncthreads();
    for (int off = 64; off; off >>= 1){
        if (tid < off) red[tid] = fmaxf(red[tid], red[tid+off]);
        __syncthreads();
    }
    float m = red[0];
    __syncthreads();
    float e = expf(sc[tid] - m);
    red[tid] = e;
    __syncthreads();
    for (int off = 64; off; off >>= 1){
        if (tid < off) red[tid] += red[tid+off];
        __syncthreads();
    }
    float s = red[0];
    __syncthreads();
    al[tid] = e / s;
    __syncthreads();
    #pragma unroll
    for (int j = 0; j < 4; j++){
        int h = tid + 128*j;
        float a = 0.f;
        const float* eo = g_enc_out + (size_t)b*CS*CH + h;
        #pragma unroll 4
        for (int ss = 0; ss < CS; ss++) a = fmaf(al[ss], eo[(size_t)ss*CH], a);
        g_CA[(size_t)bk*1024 + 512 + h] = a;
        g_CA[(size_t)bk*1024 + h] = cell[h];
    }
}
__global__ void k_acomb(){
    int i = blockIdx.x*512 + threadIdx.x;
    float a = 0.f;
    #pragma unroll
    for (int z = 0; z < 8; z++) a += g_part[(size_t)z*CBK*CH + i];
    g_attn_new[i] = a;
}
__global__ void k_lse(const float* __restrict__ bo){
    __shared__ float red[256];
    int bk = blockIdx.x, tid = threadIdx.x;
    const float* row = g_logits + (size_t)bk*CV;
    float m = -3.4e38f;
    for (int v = tid; v < CV; v += 256) m = fmaxf(m, row[v] + bo[v]);
    red[tid] = m;
    __syncthreads();
    for (int off = 128; off; off >>= 1){
        if (tid < off) red[tid] = fmaxf(red[tid], red[tid+off]);
        __syncthreads();
    }
    m = red[0];
    __syncthreads();
    float s = 0.f;
    for (int v = tid; v < CV; v += 256) s += expf(row[v] + bo[v] - m);
    red[tid] = s;
    __syncthreads();
    for (int off = 128; off; off >>= 1){
        if (tid < off) red[tid] += red[tid+off];
        __syncthreads();
    }
    if (tid == 0){ g_rmax[bk] = m; g_lse[bk] = logf(red[0]); }
}
__global__ void k_score(const float* __restrict__ bo){
    int bk = blockIdx.x;
    float cu = g_cum[bk]; int fi = g_fin[bk];
    float rm = g_rmax[bk], ls = g_lse[bk];
    float* row = g_logits + (size_t)bk*CV;
    for (int v = threadIdx.x; v < CV; v += 256){
        float val;
        if (fi) val = (v == 2) ? cu : -3.0e38f;
        else    val = cu + (((row[v] + bo[v]) - rm) - ls);
        row[v] = val;
    }
}
__global__ void k_top4(int t){
    __shared__ float sv[256];
    __shared__ int   si[256];
    __shared__ int   chosen[4];
    __shared__ float chval[4];
    int b = blockIdx.x, tid = threadIdx.x;
    const float* base = g_logits + (size_t)b*4*CV;
    for (int p = 0; p < 4; p++){
        float bv = -3.4e38f; int bi = 0x7FFFFFFF;
        for (int v = tid; v < 4*CV; v += 256){
            bool skip = false;
            for (int q = 0; q < p; q++) if (chosen[q] == v) skip = true;
            if (skip) continue;
            float x = base[v];
            if (x > bv || (x == bv && v < bi)){ bv = x; bi = v; }
        }
        sv[tid] = bv; si[tid] = bi;
        __syncthreads();
        for (int off = 128; off; off >>= 1){
            if (tid < off){
                if (sv[tid+off] > sv[tid] ||
                    (sv[tid+off] == sv[tid] && si[tid+off] < si[tid])){
                    sv[tid] = sv[tid+off]; si[tid] = si[tid+off];
                }
            }
            __syncthreads();
        }
        if (tid == 0){ chosen[p] = si[0]; chval[p] = sv[0]; }
        __syncthreads();
    }
    if (tid == 0){
        int oldfin[4];
        #pragma unroll
        for (int j = 0; j < 4; j++) oldfin[j] = g_fin[b*4+j];
        #pragma unroll
        for (int j = 0; j < 4; j++){
            int flat = chosen[j];
            int par = flat / CV, tok = flat - par*CV;
            g_cum[b*4+j] = chval[j];
            g_tok[b*4+j] = tok;
            g_fin[b*4+j] = oldfin[par] | (tok == 2);
            g_parents[t*CBK + b*4 + j] = par;
            g_toksh[t*CBK + b*4 + j]   = tok;
        }
    }
}
__global__ void k_gather(int t){
    int bk = blockIdx.x, b = bk>>2, hid = threadIdx.x;
    int par = g_parents[t*CBK + bk];
    int src = b*4 + par;
    g_h[bk*CH+hid]    = g_cell[src*CH+hid];
    g_c[bk*CH+hid]    = g_cnew[src*CH+hid];
    g_attn[bk*CH+hid] = g_attn_new[src*CH+hid];
}
// OUTPUT AS FLOAT32: token ids written as float values (see round-14 theory).
__global__ void k_backtrack(float* __restrict__ out){
    int b = threadIdx.x >> 2, j = threadIdx.x & 3;
    int d = g_diag;
    if (d){
        float code = (d & 1) ? 1.0e8f : 1.0e7f;
        for (int s = 0; s < CT; s++) out[(b*CT + s)*4 + j] = code;
        return;
    }
    int ptr = j;
    for (int s = CT-1; s >= 0; s--){
        out[(b*CT + s)*4 + j] = (float)g_toksh[s*CBK + b*4 + ptr];
        ptr = g_parents[s*CBK + b*4 + ptr];
    }
}

// ----------------- host ------------------------------------------------------
extern "C" void kernel_launch(void* const* d_in, const int* in_sizes, int n_in,
                              void* d_out, int out_size){
    // Roles (dict order): 0 enc_in, 1 dec_in(unused), 2 enc_emb, 3 dec_emb,
    // 4 W_enc, 5 U_enc, 6 b_enc, 7 W_dec, 8 U_dec, 9 b_dec, 10 W_mem,
    // 11 W_attn, 12 W_out, 13 b_out
    static const int R_SIZES[14] = {4096,1536,16384000,16384000,1048576,1048576,
                                    2048,2097152,1048576,2048,262144,524288,
                                    16384000,32000};
    const void* ptr[14];
    bool asg[14];
    for (int r = 0; r < 14; r++){ ptr[r] = 0; asg[r] = false; }
    // order-preserving greedy: i-th occurrence of a size -> i-th role of that size
    for (int i = 0; i < n_in; i++){
        for (int r = 0; r < 14; r++){
            if (!asg[r] && in_sizes[i] == R_SIZES[r]){
                asg[r] = true; ptr[r] = d_in[i]; break;
            }
        }
    }
    bool ok = true;
    for (int r = 0; r < 14; r++) if (r != 1 && !asg[r]) ok = false;
    float* out = (float*)d_out;
    if (!ok){
        k_constf<<<(out_size+255)/256,256>>>(out, out_size, 1.0e9f);
        return;
    }

    const int*   enc_in = (const int*)ptr[0];
    const float* enc_emb= (const float*)ptr[2];
    const float* dec_emb= (const float*)ptr[3];
    const float* W_enc  = (const float*)ptr[4];
    const float* U_enc  = (const float*)ptr[5];
    const float* b_enc  = (const float*)ptr[6];
    const float* W_dec  = (const float*)ptr[7];
    const float* U_dec  = (const float*)ptr[8];
    const float* b_dec  = (const float*)ptr[9];
    const float* W_mem  = (const float*)ptr[10];
    const float* W_attn = (const float*)ptr[11];
    const float* W_out  = (const float*)ptr[12];
    const float* b_out  = (const float*)ptr[13];

    k_diag0<<<1,32>>>();
    k_zero<<<64,512>>>();
    k_gatherX<<<CB*CS,256>>>(enc_in, enc_emb);
    k_catW<<<3072,1024>>>(W_dec, U_dec);
    // ZX = X @ W_enc : [4096,512]x[512,2048]
    k_g64<<<dim3(32,64,1),256>>>(0, W_enc, 512, CG, CG, 512, 0);
    for (int t = 0; t < CS; t++)
        k_enc_step<<<32,512>>>(U_enc, b_enc, t & 1, t);
    k_check_enc<<<1,256>>>();
    // keys = enc_out @ W_mem : [4096,512]x[512,512]
    k_g64<<<dim3(8,64,1),256>>>(1, W_mem, 512, 512, 512, 512, 0);
    k_dec_init<<<CBK,512>>>();

    for (int t = 0; t < CT; t++){
        k_prep<<<CBK,256>>>(dec_emb);
        // z partials: [128,1536]x[1536,2048], split-K 4 (B = internal g_Wz)
        k_g64<<<dim3(32,2,4),256>>>(2, (const float*)0, 1536, CG, CG, 384,
                                    (long long)CBK*CG);
        k_dgate<<<CBK,512>>>(b_dec);
        k_attn<<<CBK,128>>>();
        // attn_new partials: [128,1024]x[1024,512], split-K 8
        k_g64<<<dim3(8,2,8),256>>>(3, W_attn, 1024, 512, 512, 128,
                                   (long long)CBK*CH);
        k_acomb<<<128,512>>>();
        // logits: [128,512]x[512,32000]
        k_g64<<<dim3(500,2,1),256>>>(4, W_out, 512, CV, CV, 512, 0);
        k_lse<<<CBK,256>>>(b_out);
        k_score<<<CBK,256>>>(b_out);
        k_top4<<<CB,256>>>(t);
        k_gather<<<CBK,512>>>(t);
    }
    k_check_cum<<<1,128>>>();
    k_backtrack<<<1,128>>>(out);
}

// round 15
// speedup vs baseline: 1.6618x; 1.6618x over previous
#include <cuda_runtime.h>
#include <math.h>

#define CB 32
#define CS 128
#define CH 512
#define CG 2048
#define CV 32000
#define CT 48
#define CBK 128   // B*BEAM

// ----------------- device scratch (no runtime allocation) -------------------
__device__ float g_X[CB*CS*CH];
__device__ float g_ZX[CB*CS*CG];
__device__ float g_enc_out[CB*CS*CH];
__device__ float g_keys[CB*CS*CH];
__device__ float g_eh[CB*CH];
__device__ float g_eh2[CB*CH];
__device__ float g_ec[CB*CH];
__device__ float g_ec2[CB*CH];
__device__ float g_Wz[1536*CG];
__device__ float g_Ut[CH*CH*4];        // U_enc gate-interleaved: [k][hid][4]
__device__ float g_part[4*CBK*CG];
__device__ float g_XC[CBK*1536];
__device__ float g_CA[CBK*1024];
__device__ float g_h[CBK*CH];
__device__ float g_c[CBK*CH];
__device__ float g_cell[CBK*CH];
__device__ float g_cnew[CBK*CH];
__device__ float g_attn[CBK*CH];
__device__ float g_attn_new[CBK*CH];
__device__ float g_logits[CBK*CV];
__device__ float g_rmax[CBK];
__device__ float g_lse[CBK];
__device__ float g_cum[CBK];
__device__ int   g_fin[CBK];
__device__ int   g_tok[CBK];
__device__ int   g_parents[CT*CBK];
__device__ int   g_toksh[CT*CBK];

__device__ __forceinline__ float sigf(float x){ return 1.0f/(1.0f+expf(-x)); }

__device__ __forceinline__ const float* selA(int s){
    switch(s){ case 0: return g_X; case 1: return g_enc_out;
               case 2: return g_XC; case 3: return g_CA; default: return g_attn_new; }
}
__device__ __forceinline__ float* selC(int s){
    switch(s){ case 0: return g_ZX; case 1: return g_keys;
               case 2: return g_part; case 3: return g_part; default: return g_logits; }
}

// ----------------- setup kernels ---------------------------------------------
__global__ void k_constf(float* o, int n, float val){
    int i = blockIdx.x*256 + threadIdx.x;
    if (i < n) o[i] = val;
}
__global__ void k_zero(){
    int i = blockIdx.x*512 + threadIdx.x;
    if (i < CB*CH){ g_eh[i]=0.f; g_ec[i]=0.f; }
}
__global__ void k_gatherX(const int* __restrict__ enc_in,
                          const float* __restrict__ emb){
    int r = blockIdx.x;
    int tok = enc_in[r];
    g_X[(size_t)r*CH + threadIdx.x]       = emb[(size_t)tok*CH + threadIdx.x];
    g_X[(size_t)r*CH + threadIdx.x + 256] = emb[(size_t)tok*CH + threadIdx.x + 256];
}
__global__ void k_catW(const float* __restrict__ Wd, const float* __restrict__ Ud){
    int i = blockIdx.x*1024 + threadIdx.x;
    if (i >= 1536*CG) return;
    int row = i / CG, col = i % CG;
    g_Wz[i] = (row < 1024) ? Wd[i] : Ud[(size_t)(row-1024)*CG + col];
}
// Ut[(k*512+hid)*4+g] = U[k*2048 + g*512 + hid]
__global__ void k_prepU(const float* __restrict__ U){
    int i = blockIdx.x*1024 + threadIdx.x;   // 1,048,576 total
    int k = i >> 11, rem = i & 2047;
    int hid = rem >> 2, g = rem & 3;
    g_Ut[i] = U[(size_t)k*CG + g*512 + hid];
}
__global__ void k_dec_init(){
    int bk = blockIdx.x, b = bk>>2, hid = threadIdx.x;
    g_h[bk*CH+hid]    = g_eh[b*CH+hid];
    g_c[bk*CH+hid]    = g_ec[b*CH+hid];
    g_attn[bk*CH+hid] = 0.f;
    if (hid == 0){
        g_cum[bk] = ((bk&3)==0) ? 0.f : -1e9f;
        g_fin[bk] = 0;
        g_tok[bk] = 1;
    }
}

// ---- GEMM 64x64 tile, 4x4 micro (small/split-K cases) ----------------------
__global__ void k_g64(int sel, const float* __restrict__ Bext,
                      int lda, int ldb, int ldc, int kspan, long long zstr){
    __shared__ float As[16][65];
    __shared__ float Bs[16][65];
    const float* A = selA(sel);
    const float* B = Bext ? Bext : (const float*)g_Wz;
    float* C = selC(sel) + (long long)blockIdx.z * zstr;
    const int bm = blockIdx.y * 64;
    const int bn = blockIdx.x * 64;
    const int k0 = blockIdx.z * kspan;
    const int tid = threadIdx.x;
    const int tx = tid & 15, ty = tid >> 4;
    float acc[4][4];
    #pragma unroll
    for (int i=0;i<4;i++)
        #pragma unroll
        for (int j=0;j<4;j++) acc[i][j]=0.f;
    for (int kc = 0; kc < kspan; kc += 16){
        #pragma unroll
        for (int r = 0; r < 4; r++){
            int i = tid + 256*r;
            int m  = i >> 4, kk = i & 15;
            As[kk][m] = A[(size_t)(bm+m)*lda + k0 + kc + kk];
        }
        #pragma unroll
        for (int r = 0; r < 4; r++){
            int i = tid + 256*r;
            int kk = i >> 6, n = i & 63;
            Bs[kk][n] = B[(size_t)(k0+kc+kk)*ldb + bn + n];
        }
        __syncthreads();
        #pragma unroll
        for (int kk = 0; kk < 16; kk++){
            float a0=As[kk][ty],    a1=As[kk][ty+16],
                  a2=As[kk][ty+32], a3=As[kk][ty+48];
            float b0=Bs[kk][tx],    b1=Bs[kk][tx+16],
                  b2=Bs[kk][tx+32], b3=Bs[kk][tx+48];
            acc[0][0]=fmaf(a0,b0,acc[0][0]); acc[0][1]=fmaf(a0,b1,acc[0][1]);
            acc[0][2]=fmaf(a0,b2,acc[0][2]); acc[0][3]=fmaf(a0,b3,acc[0][3]);
            acc[1][0]=fmaf(a1,b0,acc[1][0]); acc[1][1]=fmaf(a1,b1,acc[1][1]);
            acc[1][2]=fmaf(a1,b2,acc[1][2]); acc[1][3]=fmaf(a1,b3,acc[1][3]);
            acc[2][0]=fmaf(a2,b0,acc[2][0]); acc[2][1]=fmaf(a2,b1,acc[2][1]);
            acc[2][2]=fmaf(a2,b2,acc[2][2]); acc[2][3]=fmaf(a2,b3,acc[2][3]);
            acc[3][0]=fmaf(a3,b0,acc[3][0]); acc[3][1]=fmaf(a3,b1,acc[3][1]);
            acc[3][2]=fmaf(a3,b2,acc[3][2]); acc[3][3]=fmaf(a3,b3,acc[3][3]);
        }
        __syncthreads();
    }
    #pragma unroll
    for (int i=0;i<4;i++)
        #pragma unroll
        for (int j=0;j<4;j++)
            C[(size_t)(bm + ty + 16*i)*ldc + bn + tx + 16*j] = acc[i][j];
}

// ---- GEMM 128x128 tile, 8x8 micro, 256 threads (logits / ZX) ----------------
__global__ void k_g128(int sel, const float* __restrict__ Bext,
                       int lda, int ldb, int ldc, int kdim){
    __shared__ float As[16][132];
    __shared__ float Bs[16][132];
    const float* A = selA(sel);
    const float* B = Bext;
    float* C = selC(sel);
    const int bm = blockIdx.y * 128;
    const int bn = blockIdx.x * 128;
    const int tid = threadIdx.x;
    const int tx = tid & 15, ty = tid >> 4;
    float acc[8][8];
    #pragma unroll
    for (int i=0;i<8;i++)
        #pragma unroll
        for (int j=0;j<8;j++) acc[i][j]=0.f;
    for (int kc = 0; kc < kdim; kc += 16){
        {   // A tile: 128 rows x 16 k, float4 along k
            int row = tid >> 2, kg = (tid & 3) * 4;
            #pragma unroll
            for (int p = 0; p < 2; p++){
                float4 a4 = *(const float4*)(A + (size_t)(bm+row+64*p)*lda + kc + kg);
                As[kg+0][row+64*p]=a4.x; As[kg+1][row+64*p]=a4.y;
                As[kg+2][row+64*p]=a4.z; As[kg+3][row+64*p]=a4.w;
            }
        }
        {   // B tile: 16 k x 128 n, float4 along n
            int kk = tid >> 5, c4 = (tid & 31) * 4;
            #pragma unroll
            for (int p = 0; p < 2; p++)
                *(float4*)(&Bs[kk+8*p][c4]) =
                    *(const float4*)(B + (size_t)(kc+kk+8*p)*ldb + bn + c4);
        }
        __syncthreads();
        #pragma unroll
        for (int kk = 0; kk < 16; kk++){
            float a[8], b[8];
            #pragma unroll
            for (int i=0;i<8;i++) a[i] = As[kk][ty + 16*i];
            #pragma unroll
            for (int j=0;j<8;j++) b[j] = Bs[kk][tx + 16*j];
            #pragma unroll
            for (int i=0;i<8;i++)
                #pragma unroll
                for (int j=0;j<8;j++)
                    acc[i][j] = fmaf(a[i], b[j], acc[i][j]);
        }
        __syncthreads();
    }
    #pragma unroll
    for (int i=0;i<8;i++)
        #pragma unroll
        for (int j=0;j<8;j++)
            C[(size_t)(bm + ty + 16*i)*ldc + bn + tx + 16*j] = acc[i][j];
}

// ----------------- encoder LSTM step (gate-interleaved U) --------------------
__global__ void k_enc_step(const float* __restrict__ bias, int par, int t){
    __shared__ float hsT[256][33];
    const float* hin = par ? g_eh2 : g_eh;
    const float* cin = par ? g_ec2 : g_ec;
    float* hout = par ? g_eh : g_eh2;
    float* cout = par ? g_ec : g_ec2;
    const float4* Ut4 = (const float4*)g_Ut;
    int tid = threadIdx.x;
    int b = tid & 31, hl = tid >> 5;
    int hid = blockIdx.x*16 + hl;
    size_t zrow = (size_t)(b*CS + t)*CG;
    float zi = g_ZX[zrow + hid]        + bias[hid];
    float zf = g_ZX[zrow + 512 + hid]  + bias[512+hid];
    float zg = g_ZX[zrow + 1024 + hid] + bias[1024+hid];
    float zo = g_ZX[zrow + 1536 + hid] + bias[1536+hid];
    for (int kc = 0; kc < CH; kc += 256){
        for (int i = tid; i < 256*32; i += 512){
            int bb = i >> 8, kk = i & 255;
            hsT[kk][bb] = hin[bb*CH + kc + kk];
        }
        __syncthreads();
        #pragma unroll 4
        for (int k = 0; k < 256; k++){
            float hv = hsT[k][b];
            float4 u = Ut4[(size_t)(kc+k)*512 + hid];
            zi = fmaf(hv, u.x, zi);
            zf = fmaf(hv, u.y, zf);
            zg = fmaf(hv, u.z, zg);
            zo = fmaf(hv, u.w, zo);
        }
        __syncthreads();
    }
    float ii = sigf(zi), ff = sigf(zf), gg = tanhf(zg), oo = sigf(zo);
    float cn = ff*cin[b*CH+hid] + ii*gg;
    cout[b*CH+hid] = cn;
    float hn = oo*tanhf(cn);
    hout[b*CH+hid] = hn;
    g_enc_out[(size_t)(b*CS+t)*CH + hid] = hn;
}

// ----------------- decoder helpers ------------------------------------------
__global__ void k_prep(const float* __restrict__ dec_emb){
    int bk = blockIdx.x;
    int tok = g_tok[bk];
    #pragma unroll
    for (int r = 0; r < 6; r++){
        int c = threadIdx.x + 256*r;
        float v;
        if (c < 512)       v = dec_emb[(size_t)tok*CH + c];
        else if (c < 1024) v = g_attn[bk*CH + c - 512];
        else               v = g_h[bk*CH + c - 1024];
        g_XC[(size_t)bk*1536 + c] = v;
    }
}
__global__ void k_dgate(const float* __restrict__ bias){
    int bk = blockIdx.x, hid = threadIdx.x;
    float zi = bias[hid], zf = bias[hid+512], zg = bias[hid+1024], zo = bias[hid+1536];
    #pragma unroll
    for (int z = 0; z < 4; z++){
        size_t base = (size_t)z*CBK*CG + (size_t)bk*CG;
        zi += g_part[base+hid];      zf += g_part[base+hid+512];
        zg += g_part[base+hid+1024]; zo += g_part[base+hid+1536];
    }
    float ii = sigf(zi), ff = sigf(zf), gg = tanhf(zg), oo = sigf(zo);
    float cn = ff*g_c[bk*CH+hid] + ii*gg;
    g_cnew[bk*CH+hid] = cn;
    g_cell[bk*CH+hid] = oo*tanhf(cn);
}
__global__ void k_attn(){
    __shared__ float cell[512];
    __shared__ float sc[128];
    __shared__ float red[128];
    __shared__ float al[128];
    int bk = blockIdx.x, b = bk >> 2;
    int tid = threadIdx.x;
    #pragma unroll
    for (int r = 0; r < 4; r++) cell[tid + 128*r] = g_cell[bk*CH + tid + 128*r];
    __syncthreads();
    {
        const float* kr = g_keys + (size_t)(b*CS + tid)*CH;
        float a = 0.f;
        #pragma unroll 4
        for (int h = 0; h < CH; h++) a = fmaf(cell[h], kr[h], a);
        sc[tid] = a; red[tid] = a;
    }
    __syncthreads();
    for (int off = 64; off; off >>= 1){
        if (tid < off) red[tid] = fmaxf(red[tid], red[tid+off]);
        __syncthreads();
    }
    float m = red[0];
    __syncthreads();
    float e = expf(sc[tid] - m);
    red[tid] = e;
    __syncthreads();
    for (int off = 64; off; off >>= 1){
        if (tid < off) red[tid] += red[tid+off];
        __syncthreads();
    }
    float s = red[0];
    __syncthreads();
    al[tid] = e / s;
    __syncthreads();
    #pragma unroll
    for (int j = 0; j < 4; j++){
        int h = tid + 128*j;
        float a = 0.f;
        const float* eo = g_enc_out + (size_t)b*CS*CH + h;
        #pragma unroll 4
        for (int ss = 0; ss < CS; ss++) a = fmaf(al[ss], eo[(size_t)ss*CH], a);
        g_CA[(size_t)bk*1024 + 512 + h] = a;
        g_CA[(size_t)bk*1024 + h] = cell[h];
    }
}
__global__ void k_acomb(){
    int i = blockIdx.x*512 + threadIdx.x;
    float a = 0.f;
    #pragma unroll
    for (int z = 0; z < 8; z++) a += g_part[(size_t)z*CBK*CH + i];
    g_attn_new[i] = a;
}
__global__ void k_lse(const float* __restrict__ bo){
    __shared__ float red[256];
    int bk = blockIdx.x, tid = threadIdx.x;
    const float* row = g_logits + (size_t)bk*CV;
    float m = -3.4e38f;
    for (int v = tid; v < CV; v += 256) m = fmaxf(m, row[v] + bo[v]);
    red[tid] = m;
    __syncthreads();
    for (int off = 128; off; off >>= 1){
        if (tid < off) red[tid] = fmaxf(red[tid], red[tid+off]);
        __syncthreads();
    }
    m = red[0];
    __syncthreads();
    float s = 0.f;
    for (int v = tid; v < CV; v += 256) s += expf(row[v] + bo[v] - m);
    red[tid] = s;
    __syncthreads();
    for (int off = 128; off; off >>= 1){
        if (tid < off) red[tid] += red[tid+off];
        __syncthreads();
    }
    if (tid == 0){ g_rmax[bk] = m; g_lse[bk] = logf(red[0]); }
}

// ---- fused score + top4: single pass, (val desc, idx asc) total order -------
__device__ __forceinline__ void ins4(float* v4, int* i4, float x, int idx){
    if (x > v4[3] || (x == v4[3] && idx < i4[3])){
        v4[3] = x; i4[3] = idx;
        #pragma unroll
        for (int j = 3; j > 0; j--){
            if (v4[j] > v4[j-1] || (v4[j] == v4[j-1] && i4[j] < i4[j-1])){
                float tv=v4[j]; v4[j]=v4[j-1]; v4[j-1]=tv;
                int ti=i4[j]; i4[j]=i4[j-1]; i4[j-1]=ti;
            }
        }
    }
}
__device__ __forceinline__ void mrg4(float* av, int* ai,
                                     const float* bv, const int* bi){
    float ov[4]; int oi[4];
    int ia = 0, ib = 0;
    #pragma unroll
    for (int q = 0; q < 4; q++){
        bool ta = (av[ia] > bv[ib]) || (av[ia] == bv[ib] && ai[ia] < bi[ib]);
        if (ta){ ov[q]=av[ia]; oi[q]=ai[ia]; ia++; }
        else   { ov[q]=bv[ib]; oi[q]=bi[ib]; ib++; }
    }
    #pragma unroll
    for (int q = 0; q < 4; q++){ av[q]=ov[q]; ai[q]=oi[q]; }
}
__global__ void k_stop4(const float* __restrict__ bo, int t){
    __shared__ float sv[256][4];
    __shared__ int   si[256][4];
    int b = blockIdx.x, tid = threadIdx.x;
    float v4[4] = {-3.4e38f,-3.4e38f,-3.4e38f,-3.4e38f};
    int   i4[4] = {0x7FFFFFFF,0x7FFFFFFF,0x7FFFFFFF,0x7FFFFFFF};
    for (int k = 0; k < 4; k++){
        int bk = b*4 + k;
        const float* row = g_logits + (size_t)bk*CV;
        float cu = g_cum[bk];
        if (g_fin[bk]){
            if (tid == 2) ins4(v4, i4, cu, k*CV + 2);
        } else {
            float rm = g_rmax[bk], ls = g_lse[bk];
            for (int v = tid; v < CV; v += 256){
                float x = cu + (((row[v] + bo[v]) - rm) - ls);
                ins4(v4, i4, x, k*CV + v);
            }
        }
    }
    #pragma unroll
    for (int q = 0; q < 4; q++){ sv[tid][q]=v4[q]; si[tid][q]=i4[q]; }
    for (int off = 128; off; off >>= 1){
        __syncthreads();
        if (tid < off) mrg4(sv[tid], si[tid], sv[tid+off], si[tid+off]);
    }
    __syncthreads();
    if (tid == 0){
        int oldfin[4];
        #pragma unroll
        for (int j = 0; j < 4; j++) oldfin[j] = g_fin[b*4+j];
        #pragma unroll
        for (int j = 0; j < 4; j++){
            int flat = si[0][j];
            int par = flat / CV, tok = flat - par*CV;
            g_cum[b*4+j] = sv[0][j];
            g_tok[b*4+j] = tok;
            g_fin[b*4+j] = oldfin[par] | (tok == 2);
            g_parents[t*CBK + b*4 + j] = par;
            g_toksh[t*CBK + b*4 + j]   = tok;
        }
    }
}
__global__ void k_gather(int t){
    int bk = blockIdx.x, b = bk>>2, hid = threadIdx.x;
    int par = g_parents[t*CBK + bk];
    int src = b*4 + par;
    g_h[bk*CH+hid]    = g_cell[src*CH+hid];
    g_c[bk*CH+hid]    = g_cnew[src*CH+hid];
    g_attn[bk*CH+hid] = g_attn_new[src*CH+hid];
}
// OUTPUT AS FLOAT32 (proven in R14)
__global__ void k_backtrack(float* __restrict__ out){
    int b = threadIdx.x >> 2, j = threadIdx.x & 3;
    int ptr = j;
    for (int s = CT-1; s >= 0; s--){
        out[(b*CT + s)*4 + j] = (float)g_toksh[s*CBK + b*4 + ptr];
        ptr = g_parents[s*CBK + b*4 + ptr];
    }
}

// ----------------- host ------------------------------------------------------
extern "C" void kernel_launch(void* const* d_in, const int* in_sizes, int n_in,
                              void* d_out, int out_size){
    // Roles (dict order): 0 enc_in, 1 dec_in(unused), 2 enc_emb, 3 dec_emb,
    // 4 W_enc, 5 U_enc, 6 b_enc, 7 W_dec, 8 U_dec, 9 b_dec, 10 W_mem,
    // 11 W_attn, 12 W_out, 13 b_out
    static const int R_SIZES[14] = {4096,1536,16384000,16384000,1048576,1048576,
                                    2048,2097152,1048576,2048,262144,524288,
                                    16384000,32000};
    const void* ptr[14];
    bool asg[14];
    for (int r = 0; r < 14; r++){ ptr[r] = 0; asg[r] = false; }
    for (int i = 0; i < n_in; i++){
        for (int r = 0; r < 14; r++){
            if (!asg[r] && in_sizes[i] == R_SIZES[r]){
                asg[r] = true; ptr[r] = d_in[i]; break;
            }
        }
    }
    bool ok = true;
    for (int r = 0; r < 14; r++) if (r != 1 && !asg[r]) ok = false;
    float* out = (float*)d_out;
    if (!ok){
        k_constf<<<(out_size+255)/256,256>>>(out, out_size, 1.0e9f);
        return;
    }

    const int*   enc_in = (const int*)ptr[0];
    const float* enc_emb= (const float*)ptr[2];
    const float* dec_emb= (const float*)ptr[3];
    const float* W_enc  = (const float*)ptr[4];
    const float* U_enc  = (const float*)ptr[5];
    const float* b_enc  = (const float*)ptr[6];
    const float* W_dec  = (const float*)ptr[7];
    const float* U_dec  = (const float*)ptr[8];
    const float* b_dec  = (const float*)ptr[9];
    const float* W_mem  = (const float*)ptr[10];
    const float* W_attn = (const float*)ptr[11];
    const float* W_out  = (const float*)ptr[12];
    const float* b_out  = (const float*)ptr[13];

    k_zero<<<64,512>>>();
    k_gatherX<<<CB*CS,256>>>(enc_in, enc_emb);
    k_catW<<<3072,1024>>>(W_dec, U_dec);
    k_prepU<<<1024,1024>>>(U_enc);
    // ZX = X @ W_enc : [4096,512]x[512,2048]
    k_g128<<<dim3(16,32),256>>>(0, W_enc, 512, CG, CG, 512);
    for (int t = 0; t < CS; t++)
        k_enc_step<<<32,512>>>(b_enc, t & 1, t);
    // keys = enc_out @ W_mem : [4096,512]x[512,512]
    k_g64<<<dim3(8,64,1),256>>>(1, W_mem, 512, 512, 512, 512, 0);
    k_dec_init<<<CBK,512>>>();

    for (int t = 0; t < CT; t++){
        k_prep<<<CBK,256>>>(dec_emb);
        // z partials: [128,1536]x[1536,2048], split-K 4 (B = internal g_Wz)
        k_g64<<<dim3(32,2,4),256>>>(2, (const float*)0, 1536, CG, CG, 384,
                                    (long long)CBK*CG);
        k_dgate<<<CBK,512>>>(b_dec);
        k_attn<<<CBK,128>>>();
        // attn_new partials: [128,1024]x[1024,512], split-K 8
        k_g64<<<dim3(8,2,8),256>>>(3, W_attn, 1024, 512, 512, 128,
                                   (long long)CBK*CH);
        k_acomb<<<128,512>>>();
        // logits: [128,512]x[512,32000]
        k_g128<<<dim3(250,1),256>>>(4, W_out, 512, CV, CV, 512);
        k_lse<<<CBK,256>>>(b_out);
        k_stop4<<<CB,256>>>(b_out, t);
        k_gather<<<CBK,512>>>(t);
    }
    k_backtrack<<<1,128>>>(out);
}

// round 16
// speedup vs baseline: 2.0900x; 1.2576x over previous
#include <cuda_runtime.h>
#include <math.h>

#define CB 32
#define CS 128
#define CH 512
#define CG 2048
#define CV 32000
#define CT 48
#define CBK 128   // B*BEAM

// ----------------- device scratch (no runtime allocation) -------------------
__device__ float g_X[CB*CS*CH];
__device__ float g_ZX[CB*CS*CG];
__device__ float g_enc_out[CB*CS*CH];
__device__ float g_keys[CB*CS*CH];
__device__ float g_eh[CB*CH];
__device__ float g_eh2[CB*CH];
__device__ float g_ec[CB*CH];
__device__ float g_ec2[CB*CH];
__device__ float g_Wz[1536*CG];
__device__ float g_Ut[CH*CH*4];        // U_enc gate-interleaved: [k][hid][4]
__device__ float g_part[4*CBK*CG];
__device__ float g_XC[CBK*1536];
__device__ float g_CA[CBK*1024];
__device__ float g_h[CBK*CH];
__device__ float g_c[CBK*CH];
__device__ float g_cell[CBK*CH];
__device__ float g_cnew[CBK*CH];
__device__ float g_attn[CBK*CH];
__device__ float g_attn_new[CBK*CH];
__device__ float g_logits[CBK*CV];
__device__ float g_cum[CBK];
__device__ int   g_fin[CBK];
__device__ int   g_tok[CBK];
__device__ int   g_parents[CT*CBK];
__device__ int   g_toksh[CT*CBK];

__device__ __forceinline__ float sigf(float x){ return 1.0f/(1.0f+expf(-x)); }

__device__ __forceinline__ const float* selA(int s){
    switch(s){ case 0: return g_X; case 1: return g_enc_out;
               case 2: return g_XC; case 3: return g_CA; default: return g_attn_new; }
}
__device__ __forceinline__ float* selC(int s){
    switch(s){ case 0: return g_ZX; case 1: return g_keys;
               case 2: return g_part; case 3: return g_part; default: return g_logits; }
}

// ----------------- setup kernels ---------------------------------------------
__global__ void k_constf(float* o, int n, float val){
    int i = blockIdx.x*256 + threadIdx.x;
    if (i < n) o[i] = val;
}
__global__ void k_zero(){
    int i = blockIdx.x*512 + threadIdx.x;
    if (i < CB*CH){ g_eh[i]=0.f; g_ec[i]=0.f; }
}
__global__ void k_gatherX(const int* __restrict__ enc_in,
                          const float* __restrict__ emb){
    int r = blockIdx.x;
    int tok = enc_in[r];
    g_X[(size_t)r*CH + threadIdx.x]       = emb[(size_t)tok*CH + threadIdx.x];
    g_X[(size_t)r*CH + threadIdx.x + 256] = emb[(size_t)tok*CH + threadIdx.x + 256];
}
__global__ void k_catW(const float* __restrict__ Wd, const float* __restrict__ Ud){
    int i = blockIdx.x*1024 + threadIdx.x;
    if (i >= 1536*CG) return;
    int row = i / CG, col = i % CG;
    g_Wz[i] = (row < 1024) ? Wd[i] : Ud[(size_t)(row-1024)*CG + col];
}
// Ut[(k*512+hid)*4+g] = U[k*2048 + g*512 + hid]
__global__ void k_prepU(const float* __restrict__ U){
    int i = blockIdx.x*1024 + threadIdx.x;   // 1,048,576 total
    int k = i >> 11, rem = i & 2047;
    int hid = rem >> 2, g = rem & 3;
    g_Ut[i] = U[(size_t)k*CG + g*512 + hid];
}
__global__ void k_dec_init(){
    int bk = blockIdx.x, b = bk>>2, hid = threadIdx.x;
    g_h[bk*CH+hid]    = g_eh[b*CH+hid];
    g_c[bk*CH+hid]    = g_ec[b*CH+hid];
    g_attn[bk*CH+hid] = 0.f;
    if (hid == 0){
        g_cum[bk] = ((bk&3)==0) ? 0.f : -1e9f;
        g_fin[bk] = 0;
        g_tok[bk] = 1;
    }
}

// ---- GEMM 64x64 tile, 4x4 micro (split-K / small cases) ---------------------
__global__ void k_g64(int sel, const float* __restrict__ Bext,
                      int lda, int ldb, int ldc, int kspan, long long zstr){
    __shared__ float As[16][65];
    __shared__ float Bs[16][65];
    const float* A = selA(sel);
    const float* B = Bext ? Bext : (const float*)g_Wz;
    float* C = selC(sel) + (long long)blockIdx.z * zstr;
    const int bm = blockIdx.y * 64;
    const int bn = blockIdx.x * 64;
    const int k0 = blockIdx.z * kspan;
    const int tid = threadIdx.x;
    const int tx = tid & 15, ty = tid >> 4;
    float acc[4][4];
    #pragma unroll
    for (int i=0;i<4;i++)
        #pragma unroll
        for (int j=0;j<4;j++) acc[i][j]=0.f;
    for (int kc = 0; kc < kspan; kc += 16){
        #pragma unroll
        for (int r = 0; r < 4; r++){
            int i = tid + 256*r;
            int m  = i >> 4, kk = i & 15;
            As[kk][m] = A[(size_t)(bm+m)*lda + k0 + kc + kk];
        }
        #pragma unroll
        for (int r = 0; r < 4; r++){
            int i = tid + 256*r;
            int kk = i >> 6, n = i & 63;
            Bs[kk][n] = B[(size_t)(k0+kc+kk)*ldb + bn + n];
        }
        __syncthreads();
        #pragma unroll
        for (int kk = 0; kk < 16; kk++){
            float a0=As[kk][ty],    a1=As[kk][ty+16],
                  a2=As[kk][ty+32], a3=As[kk][ty+48];
            float b0=Bs[kk][tx],    b1=Bs[kk][tx+16],
                  b2=Bs[kk][tx+32], b3=Bs[kk][tx+48];
            acc[0][0]=fmaf(a0,b0,acc[0][0]); acc[0][1]=fmaf(a0,b1,acc[0][1]);
            acc[0][2]=fmaf(a0,b2,acc[0][2]); acc[0][3]=fmaf(a0,b3,acc[0][3]);
            acc[1][0]=fmaf(a1,b0,acc[1][0]); acc[1][1]=fmaf(a1,b1,acc[1][1]);
            acc[1][2]=fmaf(a1,b2,acc[1][2]); acc[1][3]=fmaf(a1,b3,acc[1][3]);
            acc[2][0]=fmaf(a2,b0,acc[2][0]); acc[2][1]=fmaf(a2,b1,acc[2][1]);
            acc[2][2]=fmaf(a2,b2,acc[2][2]); acc[2][3]=fmaf(a2,b3,acc[2][3]);
            acc[3][0]=fmaf(a3,b0,acc[3][0]); acc[3][1]=fmaf(a3,b1,acc[3][1]);
            acc[3][2]=fmaf(a3,b2,acc[3][2]); acc[3][3]=fmaf(a3,b3,acc[3][3]);
        }
        __syncthreads();
    }
    #pragma unroll
    for (int i=0;i<4;i++)
        #pragma unroll
        for (int j=0;j<4;j++)
            C[(size_t)(bm + ty + 16*i)*ldc + bn + tx + 16*j] = acc[i][j];
}

// ---- GEMM 128x128 tile, 8x8 micro, vectorized LDS (logits / ZX) -------------
__global__ void __launch_bounds__(256)
k_g128(int sel, const float* __restrict__ Bext,
       int lda, int ldb, int ldc, int kdim){
    __shared__ float As[16][136];
    __shared__ float Bs[16][136];
    const float* A = selA(sel);
    const float* B = Bext;
    float* C = selC(sel);
    const int bm = blockIdx.y * 128;
    const int bn = blockIdx.x * 128;
    const int tid = threadIdx.x;
    const int tx = tid & 15, ty = tid >> 4;
    float acc[8][8];
    #pragma unroll
    for (int i=0;i<8;i++)
        #pragma unroll
        for (int j=0;j<8;j++) acc[i][j]=0.f;
    for (int kc = 0; kc < kdim; kc += 16){
        {   // A tile: 128 rows x 16 k, float4 along k
            int row = tid >> 2, kg = (tid & 3) * 4;
            #pragma unroll
            for (int p = 0; p < 2; p++){
                float4 a4 = *(const float4*)(A + (size_t)(bm+row+64*p)*lda + kc + kg);
                As[kg+0][row+64*p]=a4.x; As[kg+1][row+64*p]=a4.y;
                As[kg+2][row+64*p]=a4.z; As[kg+3][row+64*p]=a4.w;
            }
        }
        {   // B tile: 16 k x 128 n, float4 along n
            int kk = tid >> 5, c4 = (tid & 31) * 4;
            #pragma unroll
            for (int p = 0; p < 2; p++)
                *(float4*)(&Bs[kk+8*p][c4]) =
                    *(const float4*)(B + (size_t)(kc+kk+8*p)*ldb + bn + c4);
        }
        __syncthreads();
        #pragma unroll
        for (int kk = 0; kk < 16; kk++){
            float4 a0 = *(const float4*)(&As[kk][ty*4]);
            float4 a1 = *(const float4*)(&As[kk][64 + ty*4]);
            float4 b0 = *(const float4*)(&Bs[kk][tx*4]);
            float4 b1 = *(const float4*)(&Bs[kk][64 + tx*4]);
            float a[8] = {a0.x,a0.y,a0.z,a0.w,a1.x,a1.y,a1.z,a1.w};
            float b[8] = {b0.x,b0.y,b0.z,b0.w,b1.x,b1.y,b1.z,b1.w};
            #pragma unroll
            for (int i=0;i<8;i++)
                #pragma unroll
                for (int j=0;j<8;j++)
                    acc[i][j] = fmaf(a[i], b[j], acc[i][j]);
        }
        __syncthreads();
    }
    #pragma unroll
    for (int i=0;i<8;i++){
        int row = bm + ((i < 4) ? (ty*4 + i) : (64 + ty*4 + i - 4));
        float4 v0 = make_float4(acc[i][0],acc[i][1],acc[i][2],acc[i][3]);
        float4 v1 = make_float4(acc[i][4],acc[i][5],acc[i][6],acc[i][7]);
        *(float4*)(C + (size_t)row*ldc + bn + tx*4)      = v0;
        *(float4*)(C + (size_t)row*ldc + bn + 64 + tx*4) = v1;
    }
}

// ----------------- encoder LSTM step (smem-staged Ut + h) --------------------
__global__ void k_enc_step(const float* __restrict__ bias, int par, int t){
    __shared__ float Hs[64][33];
    __shared__ float Us[64][72];
    const float* hin = par ? g_eh2 : g_eh;
    const float* cin = par ? g_ec2 : g_ec;
    float* hout = par ? g_eh : g_eh2;
    float* cout = par ? g_ec : g_ec2;
    int tid = threadIdx.x;
    int b = tid & 31, hl = tid >> 5;
    int hid0 = blockIdx.x*16;
    int hid = hid0 + hl;
    size_t zrow = (size_t)(b*CS + t)*CG;
    float zi = g_ZX[zrow + hid]        + bias[hid];
    float zf = g_ZX[zrow + 512 + hid]  + bias[512+hid];
    float zg = g_ZX[zrow + 1024 + hid] + bias[1024+hid];
    float zo = g_ZX[zrow + 1536 + hid] + bias[1536+hid];
    for (int kc = 0; kc < CH; kc += 64){
        #pragma unroll
        for (int r = 0; r < 4; r++){
            int i = tid + 512*r;            // 2048 floats
            int bb = i >> 6, kk = i & 63;
            Hs[kk][bb] = hin[bb*CH + kc + kk];
        }
        #pragma unroll
        for (int r = 0; r < 8; r++){
            int i = tid + 512*r;            // 4096 floats
            int kk = i >> 6, q = i & 63;
            Us[kk][q] = g_Ut[(size_t)(kc+kk)*2048 + hid0*4 + q];
        }
        __syncthreads();
        #pragma unroll 8
        for (int k = 0; k < 64; k++){
            float hv = Hs[k][b];
            float4 u = *(const float4*)(&Us[k][hl*4]);
            zi = fmaf(hv, u.x, zi);
            zf = fmaf(hv, u.y, zf);
            zg = fmaf(hv, u.z, zg);
            zo = fmaf(hv, u.w, zo);
        }
        __syncthreads();
    }
    float ii = sigf(zi), ff = sigf(zf), gg = tanhf(zg), oo = sigf(zo);
    float cn = ff*cin[b*CH+hid] + ii*gg;
    cout[b*CH+hid] = cn;
    float hn = oo*tanhf(cn);
    hout[b*CH+hid] = hn;
    g_enc_out[(size_t)(b*CS+t)*CH + hid] = hn;
}

// ----------------- decoder helpers ------------------------------------------
__global__ void k_prep(const float* __restrict__ dec_emb){
    int bk = blockIdx.x;
    int tok = g_tok[bk];
    #pragma unroll
    for (int r = 0; r < 6; r++){
        int c = threadIdx.x + 256*r;
        float v;
        if (c < 512)       v = dec_emb[(size_t)tok*CH + c];
        else if (c < 1024) v = g_attn[bk*CH + c - 512];
        else               v = g_h[bk*CH + c - 1024];
        g_XC[(size_t)bk*1536 + c] = v;
    }
}
// fused dgate + attention (one block per beam, 512 threads)
__global__ void k_datt(const float* __restrict__ bias){
    __shared__ float cell[512];
    __shared__ float sc[128];
    __shared__ float red[128];
    __shared__ float al[128];
    int bk = blockIdx.x, b = bk >> 2;
    int tid = threadIdx.x;
    {   // dgate: hid = tid
        int hid = tid;
        float zi = bias[hid], zf = bias[hid+512], zg = bias[hid+1024], zo = bias[hid+1536];
        #pragma unroll
        for (int z = 0; z < 4; z++){
            size_t base = (size_t)z*CBK*CG + (size_t)bk*CG;
            zi += g_part[base+hid];      zf += g_part[base+hid+512];
            zg += g_part[base+hid+1024]; zo += g_part[base+hid+1536];
        }
        float ii = sigf(zi), ff = sigf(zf), gg = tanhf(zg), oo = sigf(zo);
        float cn = ff*g_c[bk*CH+hid] + ii*gg;
        g_cnew[bk*CH+hid] = cn;
        float cl = oo*tanhf(cn);
        g_cell[bk*CH+hid] = cl;
        cell[hid] = cl;
    }
    __syncthreads();
    if (tid < 128){   // scores
        const float* kr = g_keys + (size_t)(b*CS + tid)*CH;
        float a = 0.f;
        #pragma unroll 4
        for (int h = 0; h < CH; h++) a = fmaf(cell[h], kr[h], a);
        sc[tid] = a; red[tid] = a;
    }
    __syncthreads();
    for (int off = 64; off; off >>= 1){
        if (tid < off) red[tid] = fmaxf(red[tid], red[tid+off]);
        __syncthreads();
    }
    float m = red[0];
    __syncthreads();
    float e = 0.f;
    if (tid < 128){ e = expf(sc[tid] - m); red[tid] = e; }
    __syncthreads();
    for (int off = 64; off; off >>= 1){
        if (tid < off) red[tid] += red[tid+off];
        __syncthreads();
    }
    float s = red[0];
    __syncthreads();
    if (tid < 128) al[tid] = e / s;
    __syncthreads();
    {   // ctx: h = tid
        int h = tid;
        float a = 0.f;
        const float* eo = g_enc_out + (size_t)b*CS*CH + h;
        #pragma unroll 4
        for (int ss = 0; ss < CS; ss++) a = fmaf(al[ss], eo[(size_t)ss*CH], a);
        g_CA[(size_t)bk*1024 + 512 + h] = a;
        g_CA[(size_t)bk*1024 + h] = cell[h];
    }
}
__global__ void k_acomb(){
    int i = blockIdx.x*512 + threadIdx.x;
    float a = 0.f;
    #pragma unroll
    for (int z = 0; z < 8; z++) a += g_part[(size_t)z*CBK*CH + i];
    g_attn_new[i] = a;
}

// ---- fused lse + score + top4 -----------------------------------------------
__device__ __forceinline__ void ins4(float* v4, int* i4, float x, int idx){
    if (x > v4[3] || (x == v4[3] && idx < i4[3])){
        v4[3] = x; i4[3] = idx;
        #pragma unroll
        for (int j = 3; j > 0; j--){
            if (v4[j] > v4[j-1] || (v4[j] == v4[j-1] && i4[j] < i4[j-1])){
                float tv=v4[j]; v4[j]=v4[j-1]; v4[j-1]=tv;
                int ti=i4[j]; i4[j]=i4[j-1]; i4[j-1]=ti;
            }
        }
    }
}
__device__ __forceinline__ void mrg4(float* av, int* ai,
                                     const float* bv, const int* bi){
    float ov[4]; int oi[4];
    int ia = 0, ib = 0;
    #pragma unroll
    for (int q = 0; q < 4; q++){
        bool ta = (av[ia] > bv[ib]) || (av[ia] == bv[ib] && ai[ia] < bi[ib]);
        if (ta){ ov[q]=av[ia]; oi[q]=ai[ia]; ia++; }
        else   { ov[q]=bv[ib]; oi[q]=bi[ib]; ib++; }
    }
    #pragma unroll
    for (int q = 0; q < 4; q++){ av[q]=ov[q]; ai[q]=oi[q]; }
}
__global__ void k_lstop(const float* __restrict__ bo, int t){
    __shared__ float sv[256][4];
    __shared__ int   si[256][4];
    __shared__ float red[256];
    __shared__ float rms[4], lss[4];
    int b = blockIdx.x, tid = threadIdx.x;
    // per-beam log-sum-exp (identical arithmetic to old k_lse)
    for (int k = 0; k < 4; k++){
        int bk = b*4 + k;
        int fin = g_fin[bk];
        const float* row = g_logits + (size_t)bk*CV;
        float m = -3.4e38f;
        if (!fin)
            for (int v = tid; v < CV; v += 256) m = fmaxf(m, row[v] + bo[v]);
        red[tid] = m;
        __syncthreads();
        for (int off = 128; off; off >>= 1){
            if (tid < off) red[tid] = fmaxf(red[tid], red[tid+off]);
            __syncthreads();
        }
        m = red[0];
        __syncthreads();
        float s = 0.f;
        if (!fin)
            for (int v = tid; v < CV; v += 256) s += expf(row[v] + bo[v] - m);
        red[tid] = s;
        __syncthreads();
        for (int off = 128; off; off >>= 1){
            if (tid < off) red[tid] += red[tid+off];
            __syncthreads();
        }
        if (tid == 0){ rms[k] = m; lss[k] = logf(red[0]); }
        __syncthreads();
    }
    // score + per-thread top4
    float v4[4] = {-3.4e38f,-3.4e38f,-3.4e38f,-3.4e38f};
    int   i4[4] = {0x7FFFFFFF,0x7FFFFFFF,0x7FFFFFFF,0x7FFFFFFF};
    for (int k = 0; k < 4; k++){
        int bk = b*4 + k;
        const float* row = g_logits + (size_t)bk*CV;
        float cu = g_cum[bk];
        if (g_fin[bk]){
            if (tid == 2) ins4(v4, i4, cu, k*CV + 2);
        } else {
            float rm = rms[k], ls = lss[k];
            for (int v = tid; v < CV; v += 256){
                float x = cu + (((row[v] + bo[v]) - rm) - ls);
                ins4(v4, i4, x, k*CV + v);
            }
        }
    }
    #pragma unroll
    for (int q = 0; q < 4; q++){ sv[tid][q]=v4[q]; si[tid][q]=i4[q]; }
    for (int off = 128; off; off >>= 1){
        __syncthreads();
        if (tid < off) mrg4(sv[tid], si[tid], sv[tid+off], si[tid+off]);
    }
    __syncthreads();
    if (tid == 0){
        int oldfin[4];
        #pragma unroll
        for (int j = 0; j < 4; j++) oldfin[j] = g_fin[b*4+j];
        #pragma unroll
        for (int j = 0; j < 4; j++){
            int flat = si[0][j];
            int par = flat / CV, tok = flat - par*CV;
            g_cum[b*4+j] = sv[0][j];
            g_tok[b*4+j] = tok;
            g_fin[b*4+j] = oldfin[par] | (tok == 2);
            g_parents[t*CBK + b*4 + j] = par;
            g_toksh[t*CBK + b*4 + j]   = tok;
        }
    }
}
__global__ void k_gather(int t){
    int bk = blockIdx.x, b = bk>>2, hid = threadIdx.x;
    int par = g_parents[t*CBK + bk];
    int src = b*4 + par;
    g_h[bk*CH+hid]    = g_cell[src*CH+hid];
    g_c[bk*CH+hid]    = g_cnew[src*CH+hid];
    g_attn[bk*CH+hid] = g_attn_new[src*CH+hid];
}
// OUTPUT AS FLOAT32 (proven in R14)
__global__ void k_backtrack(float* __restrict__ out){
    int b = threadIdx.x >> 2, j = threadIdx.x & 3;
    int ptr = j;
    for (int s = CT-1; s >= 0; s--){
        out[(b*CT + s)*4 + j] = (float)g_toksh[s*CBK + b*4 + ptr];
        ptr = g_parents[s*CBK + b*4 + ptr];
    }
}

// ----------------- host ------------------------------------------------------
extern "C" void kernel_launch(void* const* d_in, const int* in_sizes, int n_in,
                              void* d_out, int out_size){
    // Roles (dict order): 0 enc_in, 1 dec_in(unused), 2 enc_emb, 3 dec_emb,
    // 4 W_enc, 5 U_enc, 6 b_enc, 7 W_dec, 8 U_dec, 9 b_dec, 10 W_mem,
    // 11 W_attn, 12 W_out, 13 b_out
    static const int R_SIZES[14] = {4096,1536,16384000,16384000,1048576,1048576,
                                    2048,2097152,1048576,2048,262144,524288,
                                    16384000,32000};
    const void* ptr[14];
    bool asg[14];
    for (int r = 0; r < 14; r++){ ptr[r] = 0; asg[r] = false; }
    for (int i = 0; i < n_in; i++){
        for (int r = 0; r < 14; r++){
            if (!asg[r] && in_sizes[i] == R_SIZES[r]){
                asg[r] = true; ptr[r] = d_in[i]; break;
            }
        }
    }
    bool ok = true;
    for (int r = 0; r < 14; r++) if (r != 1 && !asg[r]) ok = false;
    float* out = (float*)d_out;
    if (!ok){
        k_constf<<<(out_size+255)/256,256>>>(out, out_size, 1.0e9f);
        return;
    }

    const int*   enc_in = (const int*)ptr[0];
    const float* enc_emb= (const float*)ptr[2];
    const float* dec_emb= (const float*)ptr[3];
    const float* W_enc  = (const float*)ptr[4];
    const float* U_enc  = (const float*)ptr[5];
    const float* b_enc  = (const float*)ptr[6];
    const float* W_dec  = (const float*)ptr[7];
    const float* U_dec  = (const float*)ptr[8];
    const float* b_dec  = (const float*)ptr[9];
    const float* W_mem  = (const float*)ptr[10];
    const float* W_attn = (const float*)ptr[11];
    const float* W_out  = (const float*)ptr[12];
    const float* b_out  = (const float*)ptr[13];

    k_zero<<<64,512>>>();
    k_gatherX<<<CB*CS,256>>>(enc_in, enc_emb);
    k_catW<<<3072,1024>>>(W_dec, U_dec);
    k_prepU<<<1024,1024>>>(U_enc);
    // ZX = X @ W_enc : [4096,512]x[512,2048]
    k_g128<<<dim3(16,32),256>>>(0, W_enc, 512, CG, CG, 512);
    for (int t = 0; t < CS; t++)
        k_enc_step<<<32,512>>>(b_enc, t & 1, t);
    // keys = enc_out @ W_mem : [4096,512]x[512,512]
    k_g64<<<dim3(8,64,1),256>>>(1, W_mem, 512, 512, 512, 512, 0);
    k_dec_init<<<CBK,512>>>();

    for (int t = 0; t < CT; t++){
        k_prep<<<CBK,256>>>(dec_emb);
        // z partials: [128,1536]x[1536,2048], split-K 4 (B = internal g_Wz)
        k_g64<<<dim3(32,2,4),256>>>(2, (const float*)0, 1536, CG, CG, 384,
                                    (long long)CBK*CG);
        k_datt<<<CBK,512>>>(b_dec);
        // attn_new partials: [128,1024]x[1024,512], split-K 8
        k_g64<<<dim3(8,2,8),256>>>(3, W_attn, 1024, 512, 512, 128,
                                   (long long)CBK*CH);
        k_acomb<<<128,512>>>();
        // logits: [128,512]x[512,32000]
        k_g128<<<dim3(250,1),256>>>(4, W_out, 512, CV, CV, 512);
        k_lstop<<<CB,256>>>(b_out, t);
        k_gather<<<CBK,512>>>(t);
    }
    k_backtrack<<<1,128>>>(out);
}

// round 17
// speedup vs baseline: 2.7775x; 1.3290x over previous
#include <cuda_runtime.h>
#include <math.h>

#define CB 32
#define CS 128
#define CH 512
#define CG 2048
#define CV 32000
#define CT 48
#define CBK 128   // B*BEAM

// ----------------- device scratch (no runtime allocation) -------------------
__device__ float g_X[CB*CS*CH];
__device__ float g_ZX[CB*CS*CG];
__device__ float g_enc_out[CB*CS*CH];
__device__ float g_keys[CB*CS*CH];
__device__ float g_eh[CB*CH];
__device__ float g_eh2[CB*CH];
__device__ float g_ec[CB*CH];
__device__ float g_ec2[CB*CH];
__device__ float g_Wz[1536*CG];
__device__ float g_Ut[CH*CH*4];        // U_enc gate-interleaved: [k][hid][4]
__device__ float g_part[4*CBK*CG];
__device__ float g_XC[CBK*1536];
__device__ float g_CA[CBK*1024];
__device__ float g_h[CBK*CH];
__device__ float g_c[CBK*CH];
__device__ float g_cell[CBK*CH];
__device__ float g_cnew[CBK*CH];
__device__ float g_attn[CBK*CH];
__device__ float g_attn_new[CBK*CH];
__device__ float g_logits[CBK*CV];
__device__ float g_cum[CBK];
__device__ int   g_fin[CBK];
__device__ int   g_tok[CBK];
__device__ float g_cvals[CBK*4];
__device__ int   g_cidx[CBK*4];
__device__ int   g_parents[CT*CBK];
__device__ int   g_toksh[CT*CBK];

__device__ __forceinline__ float sigf(float x){ return 1.0f/(1.0f+expf(-x)); }

__device__ __forceinline__ const float* selA(int s){
    switch(s){ case 0: return g_X; case 1: return g_enc_out;
               case 2: return g_XC; case 3: return g_CA; default: return g_attn_new; }
}
__device__ __forceinline__ float* selC(int s){
    switch(s){ case 0: return g_ZX; case 1: return g_keys;
               case 2: return g_part; case 3: return g_part; default: return g_logits; }
}

// ----------------- setup kernels ---------------------------------------------
__global__ void k_constf(float* o, int n, float val){
    int i = blockIdx.x*256 + threadIdx.x;
    if (i < n) o[i] = val;
}
__global__ void k_zero(){
    int i = blockIdx.x*512 + threadIdx.x;
    if (i < CB*CH){ g_eh[i]=0.f; g_ec[i]=0.f; }
}
__global__ void k_gatherX(const int* __restrict__ enc_in,
                          const float* __restrict__ emb){
    int r = blockIdx.x;
    int tok = enc_in[r];
    g_X[(size_t)r*CH + threadIdx.x]       = emb[(size_t)tok*CH + threadIdx.x];
    g_X[(size_t)r*CH + threadIdx.x + 256] = emb[(size_t)tok*CH + threadIdx.x + 256];
}
__global__ void k_catW(const float* __restrict__ Wd, const float* __restrict__ Ud){
    int i = blockIdx.x*1024 + threadIdx.x;
    if (i >= 1536*CG) return;
    int row = i / CG, col = i % CG;
    g_Wz[i] = (row < 1024) ? Wd[i] : Ud[(size_t)(row-1024)*CG + col];
}
// Ut[(k*512+hid)*4+g] = U[k*2048 + g*512 + hid]
__global__ void k_prepU(const float* __restrict__ U){
    int i = blockIdx.x*1024 + threadIdx.x;   // 1,048,576 total
    int k = i >> 11, rem = i & 2047;
    int hid = rem >> 2, g = rem & 3;
    g_Ut[i] = U[(size_t)k*CG + g*512 + hid];
}
__global__ void k_dec_init(){
    int bk = blockIdx.x, b = bk>>2, hid = threadIdx.x;
    g_h[bk*CH+hid]    = g_eh[b*CH+hid];
    g_c[bk*CH+hid]    = g_ec[b*CH+hid];
    g_attn[bk*CH+hid] = 0.f;
    if (hid == 0){
        g_cum[bk] = ((bk&3)==0) ? 0.f : -1e9f;
        g_fin[bk] = 0;
        g_tok[bk] = 1;
    }
}

// ---- GEMM 64x64 tile, 4x4 micro (split-K / small cases) ---------------------
__global__ void k_g64(int sel, const float* __restrict__ Bext,
                      int lda, int ldb, int ldc, int kspan, long long zstr){
    __shared__ float As[16][65];
    __shared__ float Bs[16][65];
    const float* A = selA(sel);
    const float* B = Bext ? Bext : (const float*)g_Wz;
    float* C = selC(sel) + (long long)blockIdx.z * zstr;
    const int bm = blockIdx.y * 64;
    const int bn = blockIdx.x * 64;
    const int k0 = blockIdx.z * kspan;
    const int tid = threadIdx.x;
    const int tx = tid & 15, ty = tid >> 4;
    float acc[4][4];
    #pragma unroll
    for (int i=0;i<4;i++)
        #pragma unroll
        for (int j=0;j<4;j++) acc[i][j]=0.f;
    for (int kc = 0; kc < kspan; kc += 16){
        #pragma unroll
        for (int r = 0; r < 4; r++){
            int i = tid + 256*r;
            int m  = i >> 4, kk = i & 15;
            As[kk][m] = A[(size_t)(bm+m)*lda + k0 + kc + kk];
        }
        #pragma unroll
        for (int r = 0; r < 4; r++){
            int i = tid + 256*r;
            int kk = i >> 6, n = i & 63;
            Bs[kk][n] = B[(size_t)(k0+kc+kk)*ldb + bn + n];
        }
        __syncthreads();
        #pragma unroll
        for (int kk = 0; kk < 16; kk++){
            float a0=As[kk][ty],    a1=As[kk][ty+16],
                  a2=As[kk][ty+32], a3=As[kk][ty+48];
            float b0=Bs[kk][tx],    b1=Bs[kk][tx+16],
                  b2=Bs[kk][tx+32], b3=Bs[kk][tx+48];
            acc[0][0]=fmaf(a0,b0,acc[0][0]); acc[0][1]=fmaf(a0,b1,acc[0][1]);
            acc[0][2]=fmaf(a0,b2,acc[0][2]); acc[0][3]=fmaf(a0,b3,acc[0][3]);
            acc[1][0]=fmaf(a1,b0,acc[1][0]); acc[1][1]=fmaf(a1,b1,acc[1][1]);
            acc[1][2]=fmaf(a1,b2,acc[1][2]); acc[1][3]=fmaf(a1,b3,acc[1][3]);
            acc[2][0]=fmaf(a2,b0,acc[2][0]); acc[2][1]=fmaf(a2,b1,acc[2][1]);
            acc[2][2]=fmaf(a2,b2,acc[2][2]); acc[2][3]=fmaf(a2,b3,acc[2][3]);
            acc[3][0]=fmaf(a3,b0,acc[3][0]); acc[3][1]=fmaf(a3,b1,acc[3][1]);
            acc[3][2]=fmaf(a3,b2,acc[3][2]); acc[3][3]=fmaf(a3,b3,acc[3][3]);
        }
        __syncthreads();
    }
    #pragma unroll
    for (int i=0;i<4;i++)
        #pragma unroll
        for (int j=0;j<4;j++)
            C[(size_t)(bm + ty + 16*i)*ldc + bn + tx + 16*j] = acc[i][j];
}

// ---- GEMM 128x128 tile, 8x8 micro, double-buffered smem ---------------------
__global__ void __launch_bounds__(256)
k_g128(int sel, const float* __restrict__ Bext,
       int lda, int ldb, int ldc, int kdim){
    __shared__ float As[2][16][136];
    __shared__ float Bs[2][16][136];
    const float* A = selA(sel);
    const float* B = Bext;
    float* C = selC(sel);
    const int bm = blockIdx.y * 128;
    const int bn = blockIdx.x * 128;
    const int tid = threadIdx.x;
    const int tx = tid & 15, ty = tid >> 4;
    const int arow = tid >> 2, akg = (tid & 3) * 4;
    const int bkk = tid >> 5, bc4 = (tid & 31) * 4;
    float acc[8][8];
    #pragma unroll
    for (int i=0;i<8;i++)
        #pragma unroll
        for (int j=0;j<8;j++) acc[i][j]=0.f;

    float4 ra0, ra1, rb0, rb1;
    // prefetch tile 0
    ra0 = *(const float4*)(A + (size_t)(bm+arow)*lda + akg);
    ra1 = *(const float4*)(A + (size_t)(bm+arow+64)*lda + akg);
    rb0 = *(const float4*)(B + (size_t)(bkk)*ldb + bn + bc4);
    rb1 = *(const float4*)(B + (size_t)(bkk+8)*ldb + bn + bc4);
    int buf = 0;
    As[0][akg+0][arow]=ra0.x; As[0][akg+1][arow]=ra0.y;
    As[0][akg+2][arow]=ra0.z; As[0][akg+3][arow]=ra0.w;
    As[0][akg+0][arow+64]=ra1.x; As[0][akg+1][arow+64]=ra1.y;
    As[0][akg+2][arow+64]=ra1.z; As[0][akg+3][arow+64]=ra1.w;
    *(float4*)(&Bs[0][bkk][bc4])   = rb0;
    *(float4*)(&Bs[0][bkk+8][bc4]) = rb1;
    __syncthreads();

    for (int kc = 0; kc < kdim; kc += 16){
        int nkc = kc + 16;
        if (nkc < kdim){   // prefetch next tile into regs
            ra0 = *(const float4*)(A + (size_t)(bm+arow)*lda + nkc + akg);
            ra1 = *(const float4*)(A + (size_t)(bm+arow+64)*lda + nkc + akg);
            rb0 = *(const float4*)(B + (size_t)(nkc+bkk)*ldb + bn + bc4);
            rb1 = *(const float4*)(B + (size_t)(nkc+bkk+8)*ldb + bn + bc4);
        }
        #pragma unroll
        for (int kk = 0; kk < 16; kk++){
            float4 a0 = *(const float4*)(&As[buf][kk][ty*4]);
            float4 a1 = *(const float4*)(&As[buf][kk][64 + ty*4]);
            float4 b0 = *(const float4*)(&Bs[buf][kk][tx*4]);
            float4 b1 = *(const float4*)(&Bs[buf][kk][64 + tx*4]);
            float a[8] = {a0.x,a0.y,a0.z,a0.w,a1.x,a1.y,a1.z,a1.w};
            float b[8] = {b0.x,b0.y,b0.z,b0.w,b1.x,b1.y,b1.z,b1.w};
            #pragma unroll
            for (int i=0;i<8;i++)
                #pragma unroll
                for (int j=0;j<8;j++)
                    acc[i][j] = fmaf(a[i], b[j], acc[i][j]);
        }
        if (nkc < kdim){
            int nb = buf ^ 1;
            As[nb][akg+0][arow]=ra0.x; As[nb][akg+1][arow]=ra0.y;
            As[nb][akg+2][arow]=ra0.z; As[nb][akg+3][arow]=ra0.w;
            As[nb][akg+0][arow+64]=ra1.x; As[nb][akg+1][arow+64]=ra1.y;
            As[nb][akg+2][arow+64]=ra1.z; As[nb][akg+3][arow+64]=ra1.w;
            *(float4*)(&Bs[nb][bkk][bc4])   = rb0;
            *(float4*)(&Bs[nb][bkk+8][bc4]) = rb1;
            __syncthreads();
            buf = nb;
        }
    }
    #pragma unroll
    for (int i=0;i<8;i++){
        int row = bm + ((i < 4) ? (ty*4 + i) : (64 + ty*4 + i - 4));
        float4 v0 = make_float4(acc[i][0],acc[i][1],acc[i][2],acc[i][3]);
        float4 v1 = make_float4(acc[i][4],acc[i][5],acc[i][6],acc[i][7]);
        *(float4*)(C + (size_t)row*ldc + bn + tx*4)      = v0;
        *(float4*)(C + (size_t)row*ldc + bn + 64 + tx*4) = v1;
    }
}

// ----------------- encoder LSTM step (smem-staged Ut + h) --------------------
__global__ void k_enc_step(const float* __restrict__ bias, int par, int t){
    __shared__ float Hs[64][33];
    __shared__ float Us[64][72];
    const float* hin = par ? g_eh2 : g_eh;
    const float* cin = par ? g_ec2 : g_ec;
    float* hout = par ? g_eh : g_eh2;
    float* cout = par ? g_ec : g_ec2;
    int tid = threadIdx.x;
    int b = tid & 31, hl = tid >> 5;
    int hid0 = blockIdx.x*16;
    int hid = hid0 + hl;
    size_t zrow = (size_t)(b*CS + t)*CG;
    float zi = g_ZX[zrow + hid]        + bias[hid];
    float zf = g_ZX[zrow + 512 + hid]  + bias[512+hid];
    float zg = g_ZX[zrow + 1024 + hid] + bias[1024+hid];
    float zo = g_ZX[zrow + 1536 + hid] + bias[1536+hid];
    for (int kc = 0; kc < CH; kc += 64){
        #pragma unroll
        for (int r = 0; r < 4; r++){
            int i = tid + 512*r;
            int bb = i >> 6, kk = i & 63;
            Hs[kk][bb] = hin[bb*CH + kc + kk];
        }
        #pragma unroll
        for (int r = 0; r < 8; r++){
            int i = tid + 512*r;
            int kk = i >> 6, q = i & 63;
            Us[kk][q] = g_Ut[(size_t)(kc+kk)*2048 + hid0*4 + q];
        }
        __syncthreads();
        #pragma unroll 8
        for (int k = 0; k < 64; k++){
            float hv = Hs[k][b];
            float4 u = *(const float4*)(&Us[k][hl*4]);
            zi = fmaf(hv, u.x, zi);
            zf = fmaf(hv, u.y, zf);
            zg = fmaf(hv, u.z, zg);
            zo = fmaf(hv, u.w, zo);
        }
        __syncthreads();
    }
    float ii = sigf(zi), ff = sigf(zf), gg = tanhf(zg), oo = sigf(zo);
    float cn = ff*cin[b*CH+hid] + ii*gg;
    cout[b*CH+hid] = cn;
    float hn = oo*tanhf(cn);
    hout[b*CH+hid] = hn;
    g_enc_out[(size_t)(b*CS+t)*CH + hid] = hn;
}

// ----------------- decoder helpers ------------------------------------------
// fused gather(t-1) + XC build
__global__ void k_gprep(const float* __restrict__ dec_emb, int t){
    int bk = blockIdx.x, b = bk >> 2, tid = threadIdx.x;
    int tok = g_tok[bk];
    if (t == 0){
        #pragma unroll
        for (int r = 0; r < 6; r++){
            int c = tid + 256*r;
            float v;
            if (c < 512)       v = dec_emb[(size_t)tok*CH + c];
            else if (c < 1024) v = g_attn[bk*CH + c - 512];
            else               v = g_h[bk*CH + c - 1024];
            g_XC[(size_t)bk*1536 + c] = v;
        }
    } else {
        int par = g_parents[(t-1)*CBK + bk];
        int src = b*4 + par;
        #pragma unroll
        for (int r = 0; r < 6; r++){
            int c = tid + 256*r;
            float v;
            if (c < 512)       v = dec_emb[(size_t)tok*CH + c];
            else if (c < 1024) v = g_attn_new[src*CH + c - 512];
            else               v = g_cell[src*CH + c - 1024];
            g_XC[(size_t)bk*1536 + c] = v;
        }
        g_c[bk*CH + tid]       = g_cnew[src*CH + tid];
        g_c[bk*CH + tid + 256] = g_cnew[src*CH + tid + 256];
    }
}
// fused dgate + attention (one block per beam, 512 threads)
__global__ void k_datt(const float* __restrict__ bias){
    __shared__ float cell[512];
    __shared__ float sc[128];
    __shared__ float red[128];
    __shared__ float al[128];
    int bk = blockIdx.x, b = bk >> 2;
    int tid = threadIdx.x;
    {   // dgate: hid = tid
        int hid = tid;
        float zi = bias[hid], zf = bias[hid+512], zg = bias[hid+1024], zo = bias[hid+1536];
        #pragma unroll
        for (int z = 0; z < 4; z++){
            size_t base = (size_t)z*CBK*CG + (size_t)bk*CG;
            zi += g_part[base+hid];      zf += g_part[base+hid+512];
            zg += g_part[base+hid+1024]; zo += g_part[base+hid+1536];
        }
        float ii = sigf(zi), ff = sigf(zf), gg = tanhf(zg), oo = sigf(zo);
        float cn = ff*g_c[bk*CH+hid] + ii*gg;
        g_cnew[bk*CH+hid] = cn;
        float cl = oo*tanhf(cn);
        g_cell[bk*CH+hid] = cl;
        cell[hid] = cl;
    }
    __syncthreads();
    if (tid < 128){   // scores
        const float* kr = g_keys + (size_t)(b*CS + tid)*CH;
        float a = 0.f;
        #pragma unroll 4
        for (int h = 0; h < CH; h++) a = fmaf(cell[h], kr[h], a);
        sc[tid] = a; red[tid] = a;
    }
    __syncthreads();
    for (int off = 64; off; off >>= 1){
        if (tid < off) red[tid] = fmaxf(red[tid], red[tid+off]);
        __syncthreads();
    }
    float m = red[0];
    __syncthreads();
    float e = 0.f;
    if (tid < 128){ e = expf(sc[tid] - m); red[tid] = e; }
    __syncthreads();
    for (int off = 64; off; off >>= 1){
        if (tid < off) red[tid] += red[tid+off];
        __syncthreads();
    }
    float s = red[0];
    __syncthreads();
    if (tid < 128) al[tid] = e / s;
    __syncthreads();
    {   // ctx: h = tid
        int h = tid;
        float a = 0.f;
        const float* eo = g_enc_out + (size_t)b*CS*CH + h;
        #pragma unroll 4
        for (int ss = 0; ss < CS; ss++) a = fmaf(al[ss], eo[(size_t)ss*CH], a);
        g_CA[(size_t)bk*1024 + 512 + h] = a;
        g_CA[(size_t)bk*1024 + h] = cell[h];
    }
}
__global__ void k_acomb(){
    int i = blockIdx.x*512 + threadIdx.x;
    float a = 0.f;
    #pragma unroll
    for (int z = 0; z < 8; z++) a += g_part[(size_t)z*CBK*CH + i];
    g_attn_new[i] = a;
}

// ---- top-k helpers ----------------------------------------------------------
__device__ __forceinline__ void ins4(float* v4, int* i4, float x, int idx){
    if (x > v4[3] || (x == v4[3] && idx < i4[3])){
        v4[3] = x; i4[3] = idx;
        #pragma unroll
        for (int j = 3; j > 0; j--){
            if (v4[j] > v4[j-1] || (v4[j] == v4[j-1] && i4[j] < i4[j-1])){
                float tv=v4[j]; v4[j]=v4[j-1]; v4[j-1]=tv;
                int ti=i4[j]; i4[j]=i4[j-1]; i4[j-1]=ti;
            }
        }
    }
}
__device__ __forceinline__ void mrg4(float* av, int* ai,
                                     const float* bv, const int* bi){
    float ov[4]; int oi[4];
    int ia = 0, ib = 0;
    #pragma unroll
    for (int q = 0; q < 4; q++){
        bool ta = (av[ia] > bv[ib]) || (av[ia] == bv[ib] && ai[ia] < bi[ib]);
        if (ta){ ov[q]=av[ia]; oi[q]=ai[ia]; ia++; }
        else   { ov[q]=bv[ib]; oi[q]=bi[ib]; ib++; }
    }
    #pragma unroll
    for (int q = 0; q < 4; q++){ av[q]=ov[q]; ai[q]=oi[q]; }
}
// per-beam lse + per-beam top4 candidates (one block per beam)
__global__ void k_lse4(const float* __restrict__ bo){
    __shared__ float red[256];
    __shared__ float sv[256][4];
    __shared__ int   si[256][4];
    int bk = blockIdx.x, tid = threadIdx.x;
    int k = bk & 3;
    float cu = g_cum[bk];
    if (g_fin[bk]){
        if (tid == 0){
            g_cvals[bk*4+0] = cu;        g_cidx[bk*4+0] = k*CV + 2;
            #pragma unroll
            for (int q = 1; q < 4; q++){
                g_cvals[bk*4+q] = -3.4e38f; g_cidx[bk*4+q] = 0x7FFFFFFF;
            }
        }
        return;
    }
    const float* row = g_logits + (size_t)bk*CV;
    float m = -3.4e38f;
    for (int v = tid; v < CV; v += 256) m = fmaxf(m, row[v] + bo[v]);
    red[tid] = m;
    __syncthreads();
    for (int off = 128; off; off >>= 1){
        if (tid < off) red[tid] = fmaxf(red[tid], red[tid+off]);
        __syncthreads();
    }
    m = red[0];
    __syncthreads();
    float s = 0.f;
    for (int v = tid; v < CV; v += 256) s += expf(row[v] + bo[v] - m);
    red[tid] = s;
    __syncthreads();
    for (int off = 128; off; off >>= 1){
        if (tid < off) red[tid] += red[tid+off];
        __syncthreads();
    }
    float ls = logf(red[0]);
    float v4[4] = {-3.4e38f,-3.4e38f,-3.4e38f,-3.4e38f};
    int   i4[4] = {0x7FFFFFFF,0x7FFFFFFF,0x7FFFFFFF,0x7FFFFFFF};
    for (int v = tid; v < CV; v += 256){
        float x = cu + (((row[v] + bo[v]) - m) - ls);
        ins4(v4, i4, x, k*CV + v);
    }
    #pragma unroll
    for (int q = 0; q < 4; q++){ sv[tid][q]=v4[q]; si[tid][q]=i4[q]; }
    for (int off = 128; off; off >>= 1){
        __syncthreads();
        if (tid < off) mrg4(sv[tid], si[tid], sv[tid+off], si[tid+off]);
    }
    __syncthreads();
    if (tid == 0){
        #pragma unroll
        for (int q = 0; q < 4; q++){
            g_cvals[bk*4+q] = sv[0][q];
            g_cidx[bk*4+q]  = si[0][q];
        }
    }
}
// merge 4 beams' candidate lists, update beam state
__global__ void k_merge4(int t){
    int b = blockIdx.x;
    if (threadIdx.x != 0) return;
    float av[4]; int ai[4];
    #pragma unroll
    for (int q = 0; q < 4; q++){ av[q] = g_cvals[(b*4)*4+q]; ai[q] = g_cidx[(b*4)*4+q]; }
    for (int k = 1; k < 4; k++){
        float bv[4]; int bi[4];
        #pragma unroll
        for (int q = 0; q < 4; q++){ bv[q] = g_cvals[(b*4+k)*4+q]; bi[q] = g_cidx[(b*4+k)*4+q]; }
        mrg4(av, ai, bv, bi);
    }
    int oldfin[4];
    #pragma unroll
    for (int j = 0; j < 4; j++) oldfin[j] = g_fin[b*4+j];
    #pragma unroll
    for (int j = 0; j < 4; j++){
        int flat = ai[j];
        int par = flat / CV, tok = flat - par*CV;
        g_cum[b*4+j] = av[j];
        g_tok[b*4+j] = tok;
        g_fin[b*4+j] = oldfin[par] | (tok == 2);
        g_parents[t*CBK + b*4 + j] = par;
        g_toksh[t*CBK + b*4 + j]   = tok;
    }
}
// OUTPUT AS FLOAT32 (proven in R14)
__global__ void k_backtrack(float* __restrict__ out){
    int b = threadIdx.x >> 2, j = threadIdx.x & 3;
    int ptr = j;
    for (int s = CT-1; s >= 0; s--){
        out[(b*CT + s)*4 + j] = (float)g_toksh[s*CBK + b*4 + ptr];
        ptr = g_parents[s*CBK + b*4 + ptr];
    }
}

// ----------------- host ------------------------------------------------------
extern "C" void kernel_launch(void* const* d_in, const int* in_sizes, int n_in,
                              void* d_out, int out_size){
    // Roles (dict order): 0 enc_in, 1 dec_in(unused), 2 enc_emb, 3 dec_emb,
    // 4 W_enc, 5 U_enc, 6 b_enc, 7 W_dec, 8 U_dec, 9 b_dec, 10 W_mem,
    // 11 W_attn, 12 W_out, 13 b_out
    static const int R_SIZES[14] = {4096,1536,16384000,16384000,1048576,1048576,
                                    2048,2097152,1048576,2048,262144,524288,
                                    16384000,32000};
    const void* ptr[14];
    bool asg[14];
    for (int r = 0; r < 14; r++){ ptr[r] = 0; asg[r] = false; }
    for (int i = 0; i < n_in; i++){
        for (int r = 0; r < 14; r++){
            if (!asg[r] && in_sizes[i] == R_SIZES[r]){
                asg[r] = true; ptr[r] = d_in[i]; break;
            }
        }
    }
    bool ok = true;
    for (int r = 0; r < 14; r++) if (r != 1 && !asg[r]) ok = false;
    float* out = (float*)d_out;
    if (!ok){
        k_constf<<<(out_size+255)/256,256>>>(out, out_size, 1.0e9f);
        return;
    }

    const int*   enc_in = (const int*)ptr[0];
    const float* enc_emb= (const float*)ptr[2];
    const float* dec_emb= (const float*)ptr[3];
    const float* W_enc  = (const float*)ptr[4];
    const float* U_enc  = (const float*)ptr[5];
    const float* b_enc  = (const float*)ptr[6];
    const float* W_dec  = (const float*)ptr[7];
    const float* U_dec  = (const float*)ptr[8];
    const float* b_dec  = (const float*)ptr[9];
    const float* W_mem  = (const float*)ptr[10];
    const float* W_attn = (const float*)ptr[11];
    const float* W_out  = (const float*)ptr[12];
    const float* b_out  = (const float*)ptr[13];

    k_zero<<<64,512>>>();
    k_gatherX<<<CB*CS,256>>>(enc_in, enc_emb);
    k_catW<<<3072,1024>>>(W_dec, U_dec);
    k_prepU<<<1024,1024>>>(U_enc);
    // ZX = X @ W_enc : [4096,512]x[512,2048]
    k_g128<<<dim3(16,32),256>>>(0, W_enc, 512, CG, CG, 512);
    for (int t = 0; t < CS; t++)
        k_enc_step<<<32,512>>>(b_enc, t & 1, t);
    // keys = enc_out @ W_mem : [4096,512]x[512,512]
    k_g64<<<dim3(8,64,1),256>>>(1, W_mem, 512, 512, 512, 512, 0);
    k_dec_init<<<CBK,512>>>();

    for (int t = 0; t < CT; t++){
        k_gprep<<<CBK,256>>>(dec_emb, t);
        // z partials: [128,1536]x[1536,2048], split-K 4 (B = internal g_Wz)
        k_g64<<<dim3(32,2,4),256>>>(2, (const float*)0, 1536, CG, CG, 384,
                                    (long long)CBK*CG);
        k_datt<<<CBK,512>>>(b_dec);
        // attn_new partials: [128,1024]x[1024,512], split-K 8
        k_g64<<<dim3(8,2,8),256>>>(3, W_attn, 1024, 512, 512, 128,
                                   (long long)CBK*CH);
        k_acomb<<<128,512>>>();
        // logits: [128,512]x[512,32000]
        k_g128<<<dim3(250,1),256>>>(4, W_out, 512, CV, CV, 512);
        k_lse4<<<CBK,256>>>(b_out);
        k_merge4<<<CB,32>>>(t);
    }
    k_backtrack<<<1,128>>>(out);
}